// round 9
// baseline (speedup 1.0000x reference)
#include <cuda_runtime.h>
#include <cuda_fp16.h>
#include <mma.h>
#include <cstdint>

using namespace nvcuda;

#define N_MAX 50000
#define N_PAD (N_MAX + 128)
#define E_MAX 1600000

// Scratch (device globals; allocations are forbidden)
__device__ __align__(16) float g_h1[N_MAX * 256];
__device__ __align__(16) float g_h2[N_MAX * 64];
__device__ __align__(16) __half g_hwh[(size_t)N_PAD * 256]; // GEMM output, fp16
__device__ __align__(16) __half g_fn[(size_t)N_PAD * 512];  // normalized features fp16
__device__ __align__(16) __half g_wh[512 * 256];            // fp16 weights
__device__ float g_w[E_MAX];        // CSR-ordered edge weights
__device__ float g_hscale[N_MAX];   // row norms (h = fn * hscale)
__device__ float g_rowsum[N_MAX];
__device__ float g_deg[N_MAX];
__device__ float g_degG[N_MAX];
__device__ float g_sw[N_MAX];
__device__ float g_dinv[N_MAX];
__device__ int g_rowptr[N_MAX + 1];
__device__ int g_ofs[N_MAX];
__device__ int g_esrc[E_MAX];       // src node per CSR slot (dst-grouped)
__device__ int g_bsum[64];          // scan block sums

// ---------------------------------------------------------------------------
__global__ void clear2_kernel(float* a, float* b, int n) {
    int i = blockIdx.x * blockDim.x + threadIdx.x;
    if (i < n) { a[i] = 0.f; b[i] = 0.f; }
}

__global__ void zeroi_kernel(int* a, int n) {
    int i = blockIdx.x * blockDim.x + threadIdx.x;
    if (i < n) a[i] = 0;
}

__global__ void zeroh_kernel(__half* a, int n) {
    int i = blockIdx.x * blockDim.x + threadIdx.x;
    if (i < n) a[i] = __float2half(0.f);
}

// ---------------------------------------------------------------------------
// CSR-by-dst build
__global__ void hist_kernel(const int* __restrict__ ei, int* __restrict__ rowptr, int E) {
    int e = blockIdx.x * blockDim.x + threadIdx.x;
    if (e < E) atomicAdd(&rowptr[ei[(size_t)E + e] + 1], 1);
}

#define SCHUNK 4096
__global__ void scan1_kernel(int* __restrict__ data, int n, int* __restrict__ bsum) {
    __shared__ int ws[32];
    int tid = threadIdx.x, lane = tid & 31, w = tid >> 5;
    int base = blockIdx.x * SCHUNK;
    int idx = base + tid * 4;
    int v0 = (idx + 0 < n) ? data[idx + 0] : 0;
    int v1 = (idx + 1 < n) ? data[idx + 1] : 0;
    int v2 = (idx + 2 < n) ? data[idx + 2] : 0;
    int v3 = (idx + 3 < n) ? data[idx + 3] : 0;
    int e1 = v0 + v1, e2 = e1 + v2, e3 = e2 + v3;
    int x = e3;
    #pragma unroll
    for (int o = 1; o < 32; o <<= 1) {
        int t = __shfl_up_sync(0xffffffffu, x, o);
        if (lane >= o) x += t;
    }
    int wexcl = x - e3;
    if (lane == 31) ws[w] = x;
    __syncthreads();
    if (w == 0) {
        int s = ws[lane];
        #pragma unroll
        for (int o = 1; o < 32; o <<= 1) {
            int t = __shfl_up_sync(0xffffffffu, s, o);
            if (lane >= o) s += t;
        }
        ws[lane] = s;
    }
    __syncthreads();
    int off = ((w > 0) ? ws[w - 1] : 0) + wexcl;
    if (idx + 0 < n) data[idx + 0] = v0 + off;
    if (idx + 1 < n) data[idx + 1] = e1 + off;
    if (idx + 2 < n) data[idx + 2] = e2 + off;
    if (idx + 3 < n) data[idx + 3] = e3 + off;
    if (tid == 0) bsum[blockIdx.x] = ws[31];
}

__global__ void scan2_kernel(int* __restrict__ bsum, int nb) {
    int lane = threadIdx.x;
    int carry = 0;
    for (int base = 0; base < nb; base += 32) {
        int i = base + lane;
        int v = (i < nb) ? bsum[i] : 0;
        int x = v;
        #pragma unroll
        for (int o = 1; o < 32; o <<= 1) {
            int t = __shfl_up_sync(0xffffffffu, x, o);
            if (lane >= o) x += t;
        }
        if (i < nb) bsum[i] = x + carry;
        carry += __shfl_sync(0xffffffffu, x, 31);
    }
}

__global__ void scan3_kernel(int* __restrict__ data, int n, const int* __restrict__ bsum) {
    int b = blockIdx.x + 1;
    int base = b * SCHUNK;
    int add = bsum[b - 1];
    int idx = base + threadIdx.x * 4;
    #pragma unroll
    for (int j = 0; j < 4; j++)
        if (idx + j < n) data[idx + j] += add;
}

__global__ void copyofs_kernel(const int* __restrict__ rowptr, int* __restrict__ ofs, int n) {
    int i = blockIdx.x * blockDim.x + threadIdx.x;
    if (i < n) ofs[i] = rowptr[i];
}

__global__ void scatter_kernel(const int* __restrict__ ei, int* __restrict__ ofs,
                               int* __restrict__ esrc, int E) {
    int e = blockIdx.x * blockDim.x + threadIdx.x;
    if (e < E) {
        int pos = atomicAdd(&ofs[ei[(size_t)E + e]], 1);
        esrc[pos] = ei[e];
    }
}

// ---------------------------------------------------------------------------
// warp per node: inv L2 norm; write normalized fp16 row + row norm (hscale).
template <int VPT>
__global__ void normfn_kernel(const float* __restrict__ h, __half* __restrict__ fn,
                              float* __restrict__ hscale, int n, int d4) {
    int node = (blockIdx.x * blockDim.x + threadIdx.x) >> 5;
    int lane = threadIdx.x & 31;
    if (node >= n) return;
    const float4* row = (const float4*)h + (size_t)node * d4;
    float4 c[VPT];
    float acc = 0.f;
    #pragma unroll
    for (int v = 0; v < VPT; v++) {
        int j = lane + v * 32;
        if (j < d4) {
            float4 t = row[j];
            c[v] = t;
            acc += t.x * t.x + t.y * t.y + t.z * t.z + t.w * t.w;
        }
    }
    #pragma unroll
    for (int o = 16; o; o >>= 1) acc += __shfl_xor_sync(0xffffffffu, acc, o);
    float iv = (acc == 0.f) ? 1.f : rsqrtf(acc);
    if (lane == 0) hscale[node] = (acc == 0.f) ? 1.f : sqrtf(acc);
    uint2* frow = (uint2*)(fn + (size_t)node * (d4 * 4));
    #pragma unroll
    for (int v = 0; v < VPT; v++) {
        int j = lane + v * 32;
        if (j < d4) {
            __half2 lo = __floats2half2_rn(c[v].x * iv, c[v].y * iv);
            __half2 hi = __floats2half2_rn(c[v].z * iv, c[v].w * iv);
            uint2 u;
            u.x = *(unsigned*)&lo;
            u.y = *(unsigned*)&hi;
            frow[j] = u;
        }
    }
}

// warp per dst node: fp16 dot vs cached dst row; w in CSR order; rowsum atomics
template <int VPT>
__global__ void sim_csr_kernel(const __half* __restrict__ fn,
                               const int* __restrict__ rowptr,
                               const int* __restrict__ esrc,
                               float* __restrict__ w, float* __restrict__ rowsum,
                               int n, int d4) {
    int node = (int)(((size_t)blockIdx.x * blockDim.x + threadIdx.x) >> 5);
    int lane = threadIdx.x & 31;
    if (node >= n) return;
    const uint2* f2 = (const uint2*)fn;
    const uint2* ft = f2 + (size_t)node * d4;
    float4 cached[VPT];
    #pragma unroll
    for (int v = 0; v < VPT; v++) {
        int j = lane + v * 32;
        if (j < d4) {
            uint2 u = ft[j];
            float2 lo = __half22float2(*(__half2*)&u.x);
            float2 hi = __half22float2(*(__half2*)&u.y);
            cached[v] = make_float4(lo.x, lo.y, hi.x, hi.y);
        } else cached[v] = make_float4(0.f, 0.f, 0.f, 0.f);
    }
    int p0 = rowptr[node], p1 = rowptr[node + 1];
    for (int p = p0; p < p1; p++) {
        int s = esrc[p];
        const uint2* fs = f2 + (size_t)s * d4;
        float acc = 0.f;
        #pragma unroll
        for (int v = 0; v < VPT; v++) {
            int j = lane + v * 32;
            if (j < d4) {
                uint2 u = fs[j];
                float2 lo = __half22float2(*(__half2*)&u.x);
                float2 hi = __half22float2(*(__half2*)&u.y);
                float4 b = cached[v];
                acc += lo.x * b.x + lo.y * b.y + hi.x * b.z + hi.y * b.w;
            }
        }
        #pragma unroll
        for (int o = 16; o; o >>= 1) acc += __shfl_xor_sync(0xffffffffu, acc, o);
        if (lane == 0) {
            float wv = (s != node && acc >= 0.f) ? acc : 0.f;
            w[p] = wv;
            if (wv > 0.f) atomicAdd(&rowsum[s], wv);
        }
    }
}

__global__ void edge2_csr_kernel(const int* __restrict__ rowptr,
                                 const int* __restrict__ esrc,
                                 float* __restrict__ w,
                                 const float* __restrict__ rowsum,
                                 float* __restrict__ deg, float* __restrict__ degG,
                                 int n) {
    int t = blockIdx.x * blockDim.x + threadIdx.x;
    if (t >= n) return;
    int p0 = rowptr[t], p1 = rowptr[t + 1];
    float dsum = 0.f;
    for (int p = p0; p < p1; p++) {
        float wv = w[p];
        if (wv > 0.f) {
            int s = esrc[p];
            float ew = expf(wv / rowsum[s]);
            atomicAdd(&deg[s], 1.0f);
            dsum += ew;
            w[p] = ew;
        }
    }
    degG[t] = dsum;
}

__global__ void node2_kernel(const float* __restrict__ deg,
                             const float* __restrict__ degG,
                             float* __restrict__ sw, float* __restrict__ dinv,
                             int n) {
    int i = blockIdx.x * blockDim.x + threadIdx.x;
    if (i >= n) return;
    float s = expf(1.0f / (deg[i] + 1.0f));
    sw[i] = s;
    dinv[i] = rsqrtf(degG[i] + s);
}

// ---------------------------------------------------------------------------
// W (fp32) -> fp16
__global__ void convw_kernel(const float* __restrict__ W, __half* __restrict__ Wh, int total) {
    int i = blockIdx.x * blockDim.x + threadIdx.x;
    if (i < total) Wh[i] = __float2half(W[i]);
}

// HMMA GEMM v3: C(fp16)[n_pad x m] = A(fp16) @ Wh, fp32 accum, fp16 store.
// 256 threads = 8 warps (4 row x 2 col). Tile 128 rows x m cols. m == 32*FC.
#define AP 24          // As pitch in halves (16 data + 8 pad)
#define SP 20          // staging pitch in floats
template <int FC>
__global__ void __launch_bounds__(256) hmma2_kernel(
        const __half* __restrict__ A, const __half* __restrict__ Wh,
        __half* __restrict__ C, int k, int m) {
    __shared__ __align__(16) __half As[128 * AP];
    __shared__ __align__(16) __half Ws[16 * (32 * FC + 8)];
    __shared__ __align__(16) float stag[8][16 * SP];
    const int WP = 32 * FC + 8;    // Ws pitch in halves
    int bm = blockIdx.x * 128;
    int tid = threadIdx.x;
    int wid = tid >> 5;
    int lane = tid & 31;
    int wr = wid >> 1, wc = wid & 1;
    wmma::fragment<wmma::accumulator, 16, 16, 16, float> acc[2][FC];
    #pragma unroll
    for (int i = 0; i < 2; i++)
        #pragma unroll
        for (int f = 0; f < FC; f++) wmma::fill_fragment(acc[i][f], 0.f);
    int mdiv8 = m >> 3;
    for (int k0 = 0; k0 < k; k0 += 16) {
        {   // As: 128 rows x 16 halves
            int r = tid >> 1, seg = (tid & 1) * 8;
            *(float4*)&As[r * AP + seg] =
                *(const float4*)&A[(size_t)(bm + r) * k + k0 + seg];
        }
        for (int f = tid; f < 2 * m; f += 256) {
            int r = f / mdiv8, c = (f % mdiv8) * 8;
            *(float4*)&Ws[r * WP + c] = *(const float4*)&Wh[(size_t)(k0 + r) * m + c];
        }
        __syncthreads();
        wmma::fragment<wmma::matrix_a, 16, 16, 16, __half, wmma::row_major> fa0, fa1;
        wmma::load_matrix_sync(fa0, &As[(wr * 32) * AP], AP);
        wmma::load_matrix_sync(fa1, &As[(wr * 32 + 16) * AP], AP);
        #pragma unroll
        for (int f = 0; f < FC; f++) {
            wmma::fragment<wmma::matrix_b, 16, 16, 16, __half, wmma::row_major> fb;
            wmma::load_matrix_sync(fb, &Ws[(wc * FC + f) * 16], WP);
            wmma::mma_sync(acc[0][f], fa0, fb, acc[0][f]);
            wmma::mma_sync(acc[1][f], fa1, fb, acc[1][f]);
        }
        __syncthreads();
    }
    // Epilogue: stage fp32 frags in smem, convert to fp16, uint4 store.
    int srow = lane >> 1, sseg = (lane & 1) * 8;
    #pragma unroll
    for (int i = 0; i < 2; i++)
        #pragma unroll
        for (int f = 0; f < FC; f++) {
            wmma::store_matrix_sync(&stag[wid][0], acc[i][f], SP, wmma::mem_row_major);
            __syncwarp();
            const float* sp = &stag[wid][srow * SP + sseg];
            __half2 h0 = __floats2half2_rn(sp[0], sp[1]);
            __half2 h1 = __floats2half2_rn(sp[2], sp[3]);
            __half2 h2 = __floats2half2_rn(sp[4], sp[5]);
            __half2 h3 = __floats2half2_rn(sp[6], sp[7]);
            uint4 u;
            u.x = *(unsigned*)&h0; u.y = *(unsigned*)&h1;
            u.z = *(unsigned*)&h2; u.w = *(unsigned*)&h3;
            size_t off = (size_t)(bm + wr * 32 + i * 16 + srow) * m
                         + (wc * FC + f) * 16 + sseg;
            *(uint4*)&C[off] = u;
            __syncwarp();
        }
}

// ---------------------------------------------------------------------------
// SIMT GEMM (layer 3): 128x64 tile, 8x4 micro, fp16 output
__global__ void __launch_bounds__(256) gemm64_kernel(
        const float* __restrict__ A, const float* __restrict__ W,
        __half* __restrict__ C, int n, int k, int m) {
    __shared__ float As[16][128];
    __shared__ float Ws[16][64];
    int bm = blockIdx.y * 128;
    int bn = blockIdx.x * 64;
    int tid = threadIdx.x;
    int tr = tid >> 4, tc = tid & 15;
    float acc[8][4] = {};
    for (int k0 = 0; k0 < k; k0 += 16) {
        #pragma unroll
        for (int l = 0; l < 2; l++) {
            int f = tid * 2 + l;
            int r = f >> 2;
            int c4 = (f & 3) * 4;
            int gr = bm + r;
            float4 v = make_float4(0.f, 0.f, 0.f, 0.f);
            if (gr < n) v = *(const float4*)&A[(size_t)gr * k + k0 + c4];
            As[c4 + 0][r] = v.x; As[c4 + 1][r] = v.y;
            As[c4 + 2][r] = v.z; As[c4 + 3][r] = v.w;
        }
        {
            int r = tid >> 4;
            int c4 = (tid & 15) * 4;
            int gc = bn + c4;
            const float* wrow = &W[(size_t)(k0 + r) * m];
            float4 v;
            if (gc + 3 < m) v = *(const float4*)&wrow[gc];
            else {
                v.x = (gc + 0 < m) ? wrow[gc + 0] : 0.f;
                v.y = (gc + 1 < m) ? wrow[gc + 1] : 0.f;
                v.z = (gc + 2 < m) ? wrow[gc + 2] : 0.f;
                v.w = (gc + 3 < m) ? wrow[gc + 3] : 0.f;
            }
            *(float4*)&Ws[r][c4] = v;
        }
        __syncthreads();
        #pragma unroll
        for (int kk = 0; kk < 16; kk++) {
            float a[8];
            *(float4*)&a[0] = *(float4*)&As[kk][tr * 8];
            *(float4*)&a[4] = *(float4*)&As[kk][tr * 8 + 4];
            float4 wv = *(float4*)&Ws[kk][tc * 4];
            #pragma unroll
            for (int i = 0; i < 8; i++) {
                acc[i][0] += a[i] * wv.x;
                acc[i][1] += a[i] * wv.y;
                acc[i][2] += a[i] * wv.z;
                acc[i][3] += a[i] * wv.w;
            }
        }
        __syncthreads();
    }
    #pragma unroll
    for (int i = 0; i < 8; i++) {
        int gr = bm + tr * 8 + i;
        if (gr >= n) continue;
        int gc = bn + tc * 4;
        #pragma unroll
        for (int j = 0; j < 4; j++)
            if (gc + j < m) C[(size_t)gr * m + gc + j] = __float2half(acc[i][j]);
    }
}

// ---------------------------------------------------------------------------
// CSR aggregation: fp16 hw gather; fused self-loop + bias + relu + hscale.
template <int VPT>
__global__ void agg_csr_kernel(const int* __restrict__ rowptr,
                               const int* __restrict__ esrc,
                               const float* __restrict__ w,
                               const float* __restrict__ dinv,
                               const float* __restrict__ sw,
                               const __half* __restrict__ hw,
                               const float* __restrict__ b,
                               const float* __restrict__ hscale,
                               float* __restrict__ out,
                               int n, int m4, int relu) {
    int node = (int)(((size_t)blockIdx.x * blockDim.x + threadIdx.x) >> 5);
    int lane = threadIdx.x & 31;
    if (node >= n) return;
    float4 acc[VPT];
    #pragma unroll
    for (int v = 0; v < VPT; v++) acc[v] = make_float4(0.f, 0.f, 0.f, 0.f);
    float dt = dinv[node];
    int p0 = rowptr[node], p1 = rowptr[node + 1];
    const uint2* hw2 = (const uint2*)hw;      // 4 halves per uint2
    for (int p = p0; p < p1; p++) {
        float ew = w[p];
        if (ew == 0.f) continue;
        int s = esrc[p];
        float sc = hscale ? hscale[s] : 1.f;
        float coef = ew * dinv[s] * dt * sc;
        const uint2* row = hw2 + (size_t)s * m4;
        #pragma unroll
        for (int v = 0; v < VPT; v++) {
            int j = lane + v * 32;
            if (j < m4) {
                uint2 u = row[j];
                float2 lo = __half22float2(*(__half2*)&u.x);
                float2 hi = __half22float2(*(__half2*)&u.y);
                acc[v].x += coef * lo.x; acc[v].y += coef * lo.y;
                acc[v].z += coef * hi.x; acc[v].w += coef * hi.y;
            }
        }
    }
    float selfsc = hscale ? hscale[node] : 1.f;
    float self = sw[node] * dt * dt * selfsc;
    const uint2* srow = hw2 + (size_t)node * m4;
    float4* orow = (float4*)out + (size_t)node * m4;
    const float4* b4 = (const float4*)b;
    #pragma unroll
    for (int v = 0; v < VPT; v++) {
        int j = lane + v * 32;
        if (j < m4) {
            uint2 u = srow[j];
            float2 lo = __half22float2(*(__half2*)&u.x);
            float2 hi = __half22float2(*(__half2*)&u.y);
            float4 bv = b4[j];
            float4 r;
            r.x = acc[v].x + self * lo.x + bv.x;
            r.y = acc[v].y + self * lo.y + bv.y;
            r.z = acc[v].z + self * hi.x + bv.z;
            r.w = acc[v].w + self * hi.y + bv.w;
            if (relu) {
                r.x = fmaxf(r.x, 0.f); r.y = fmaxf(r.y, 0.f);
                r.z = fmaxf(r.z, 0.f); r.w = fmaxf(r.w, 0.f);
            }
            orow[j] = r;
        }
    }
}

// warp per row log_softmax
__global__ void lsm_kernel(float* __restrict__ out, int n, int m) {
    int row = (blockIdx.x * blockDim.x + threadIdx.x) >> 5;
    int lane = threadIdx.x & 31;
    if (row >= n) return;
    float* r = out + (size_t)row * m;
    float mx = -1e30f;
    for (int j = lane; j < m; j += 32) mx = fmaxf(mx, r[j]);
    #pragma unroll
    for (int o = 16; o; o >>= 1) mx = fmaxf(mx, __shfl_xor_sync(0xffffffffu, mx, o));
    float se = 0.f;
    for (int j = lane; j < m; j += 32) se += expf(r[j] - mx);
    #pragma unroll
    for (int o = 16; o; o >>= 1) se += __shfl_xor_sync(0xffffffffu, se, o);
    float l = mx + logf(se);
    for (int j = lane; j < m; j += 32) r[j] -= l;
}

// ---------------------------------------------------------------------------
static void run_layer(const float* h, int d, const float* W, const float* b,
                      int dout, int n,
                      __half* hwh, float* rowsum, float* deg, float* degG,
                      __half* fn, __half* wh, float* hscale,
                      float* w, float* sw, float* dinv,
                      const int* rowptr, const int* esrc,
                      float* out, bool do_relu, bool use_hmma) {
    const int T = 256;
    int d4 = d >> 2;
    clear2_kernel<<<(n + T - 1) / T, T>>>(rowsum, deg, n);
    int wb = (int)(((size_t)n * 32 + T - 1) / T);
    if (d4 > 64)       normfn_kernel<4><<<wb, T>>>(h, fn, hscale, n, d4);
    else if (d4 > 32)  normfn_kernel<2><<<wb, T>>>(h, fn, hscale, n, d4);
    else               normfn_kernel<1><<<wb, T>>>(h, fn, hscale, n, d4);
    if (d4 > 64)       sim_csr_kernel<4><<<wb, T>>>(fn, rowptr, esrc, w, rowsum, n, d4);
    else if (d4 > 32)  sim_csr_kernel<2><<<wb, T>>>(fn, rowptr, esrc, w, rowsum, n, d4);
    else               sim_csr_kernel<1><<<wb, T>>>(fn, rowptr, esrc, w, rowsum, n, d4);
    edge2_csr_kernel<<<(n + T - 1) / T, T>>>(rowptr, esrc, w, rowsum, deg, degG, n);
    node2_kernel<<<(n + T - 1) / T, T>>>(deg, degG, sw, dinv, n);
    const float* agg_hscale = nullptr;
    if (use_hmma) {
        convw_kernel<<<(d * dout + T - 1) / T, T>>>(W, wh, d * dout);
        int gb = (n + 127) / 128;
        if (dout == 256)     hmma2_kernel<8><<<gb, 256>>>(fn, wh, hwh, d, dout);
        else                 hmma2_kernel<2><<<gb, 256>>>(fn, wh, hwh, d, dout);
        agg_hscale = hscale;
    } else {
        dim3 gg((dout + 63) / 64, (n + 127) / 128);
        gemm64_kernel<<<gg, 256>>>(h, W, hwh, n, d, dout);
    }
    int m4 = dout >> 2;
    if (m4 > 32)
        agg_csr_kernel<2><<<wb, T>>>(rowptr, esrc, w, dinv, sw, hwh, b, agg_hscale,
                                     out, n, m4, do_relu ? 1 : 0);
    else
        agg_csr_kernel<1><<<wb, T>>>(rowptr, esrc, w, dinv, sw, hwh, b, agg_hscale,
                                     out, n, m4, do_relu ? 1 : 0);
}

extern "C" void kernel_launch(void* const* d_in, const int* in_sizes, int n_in,
                              void* d_out, int out_size) {
    const float* x = (const float*)d_in[0];
    const int* ei = (const int*)d_in[1];     // int32 (JAX default)
    const float* W1 = (const float*)d_in[2];
    const float* b1 = (const float*)d_in[3];
    const float* W2 = (const float*)d_in[4];
    const float* b2 = (const float*)d_in[5];
    const float* W3 = (const float*)d_in[6];
    const float* b3 = (const float*)d_in[7];
    float* out = (float*)d_out;

    int H  = in_sizes[3];          // 256
    int D2 = in_sizes[5];          // 64
    int C  = in_sizes[7];          // 40
    int F  = in_sizes[2] / H;      // 512
    int n  = in_sizes[0] / F;      // 50000
    int E  = in_sizes[1] / 2;      // 1600000

    float *p_h1, *p_h2, *p_w, *p_hscale, *p_rowsum, *p_deg, *p_degG, *p_sw, *p_dinv;
    __half *p_fn, *p_wh, *p_hwh;
    int *p_rowptr, *p_ofs, *p_esrc, *p_bsum;
    cudaGetSymbolAddress((void**)&p_h1, g_h1);
    cudaGetSymbolAddress((void**)&p_h2, g_h2);
    cudaGetSymbolAddress((void**)&p_hwh, g_hwh);
    cudaGetSymbolAddress((void**)&p_fn, g_fn);
    cudaGetSymbolAddress((void**)&p_wh, g_wh);
    cudaGetSymbolAddress((void**)&p_w, g_w);
    cudaGetSymbolAddress((void**)&p_hscale, g_hscale);
    cudaGetSymbolAddress((void**)&p_rowsum, g_rowsum);
    cudaGetSymbolAddress((void**)&p_deg, g_deg);
    cudaGetSymbolAddress((void**)&p_degG, g_degG);
    cudaGetSymbolAddress((void**)&p_sw, g_sw);
    cudaGetSymbolAddress((void**)&p_dinv, g_dinv);
    cudaGetSymbolAddress((void**)&p_rowptr, g_rowptr);
    cudaGetSymbolAddress((void**)&p_ofs, g_ofs);
    cudaGetSymbolAddress((void**)&p_esrc, g_esrc);
    cudaGetSymbolAddress((void**)&p_bsum, g_bsum);

    const int T = 256;
    // Zero the padded tail of fn once (so padded wmma A-rows are clean zeros)
    {
        int tail = 128 * 512;
        zeroh_kernel<<<(tail + T - 1) / T, T>>>(p_fn + (size_t)N_MAX * 512, tail);
    }
    // Build CSR by dst once (edge structure identical across layers)
    zeroi_kernel<<<(n + 1 + T - 1) / T, T>>>(p_rowptr, n + 1);
    hist_kernel<<<(E + T - 1) / T, T>>>(ei, p_rowptr, E);
    int nscan = n + 1;
    int nb = (nscan + SCHUNK - 1) / SCHUNK;
    scan1_kernel<<<nb, 1024>>>(p_rowptr, nscan, p_bsum);
    scan2_kernel<<<1, 32>>>(p_bsum, nb);
    if (nb > 1) scan3_kernel<<<nb - 1, 1024>>>(p_rowptr, nscan, p_bsum);
    copyofs_kernel<<<(n + T - 1) / T, T>>>(p_rowptr, p_ofs, n);
    scatter_kernel<<<(E + T - 1) / T, T>>>(ei, p_ofs, p_esrc, E);

    // Layer 1: x(512) -> h1(256), relu, HMMA
    run_layer(x, F, W1, b1, H, n, p_hwh, p_rowsum, p_deg, p_degG,
              p_fn, p_wh, p_hscale, p_w, p_sw, p_dinv, p_rowptr, p_esrc,
              p_h1, true, true);
    // Layer 2: h1(256) -> h2(64), relu, HMMA
    run_layer(p_h1, H, W2, b2, D2, n, p_hwh, p_rowsum, p_deg, p_degG,
              p_fn, p_wh, p_hscale, p_w, p_sw, p_dinv, p_rowptr, p_esrc,
              p_h2, true, true);
    // Layer 3: h2(64) -> out(40), no relu, SIMT (m=40)
    run_layer(p_h2, D2, W3, b3, C, n, p_hwh, p_rowsum, p_deg, p_degG,
              p_fn, p_wh, p_hscale, p_w, p_sw, p_dinv, p_rowptr, p_esrc,
              out, false, false);
    // log_softmax in place on d_out
    lsm_kernel<<<(n * 32 + 255) / 256, 256>>>(out, n, C);
}